// round 2
// baseline (speedup 1.0000x reference)
#include <cuda_runtime.h>

// ---------------- problem constants ----------------
#define NN      1536
#define NE      49152
#define EMB     32
#define HEADS   3
#define SLOPE   0.2f
#define MAXD    256     // max supported out-degree (Poisson(32) max ~55; huge margin)

// ---------------- device scratch (allocation-free) ----------------
__device__ float g_tar    [NN * HEADS];
__device__ float g_nbr    [NN * HEADS];
__device__ float g_nbrupd [NN * EMB];
__device__ float g_meanfall[EMB];
__device__ float g_escore [NE * 4];     // padded stride 4
__device__ float g_eupd   [NE * EMB];
__device__ int   g_deg    [NN];
__device__ int   g_rowptr [NN + 1];
__device__ int   g_rowfill[NN];
__device__ int   g_dstS   [NE];
__device__ int   g_eidS   [NE];
__device__ int   g_veh    [NN];
__device__ int   g_ped    [NN];

__device__ __forceinline__ float leaky(float x) { return x >= 0.f ? x : SLOPE * x; }

// ---------------- K_mask: dtype-agnostic decode of the boolean masks -----
// The reference emits jnp.bool_ masks; the harness may deliver them as
// int32, float32, or raw uint8 bytes. Detect by inspecting the first
// 384 words (= 1536 bytes, the minimum possible buffer size).
__global__ void k_mask(const unsigned int* __restrict__ veh_raw,
                       const unsigned int* __restrict__ ped_raw) {
    __shared__ int s_notInt, s_notF32;
    int tid = threadIdx.x;
    if (tid == 0) { s_notInt = 0; s_notF32 = 0; }
    __syncthreads();
    if (tid < 384) {
        unsigned int w = veh_raw[tid];
        if (!(w == 0u || w == 1u))           atomicOr(&s_notInt, 1);
        if (!(w == 0u || w == 0x3F800000u))  atomicOr(&s_notF32, 1);
    }
    __syncthreads();
    int dtype = (!s_notInt) ? 0 : ((!s_notF32) ? 1 : 2);  // 0=i32, 1=f32, 2=u8
    for (int i = tid; i < NN; i += blockDim.x) {
        int v, p;
        if (dtype == 0) {
            v = ((const int*)veh_raw)[i] != 0;
            p = ((const int*)ped_raw)[i] != 0;
        } else if (dtype == 1) {
            v = ((const float*)veh_raw)[i] != 0.f;
            p = ((const float*)ped_raw)[i] != 0.f;
        } else {
            v = ((const unsigned char*)veh_raw)[i] != 0;
            p = ((const unsigned char*)ped_raw)[i] != 0;
        }
        g_veh[i] = v; g_ped[i] = p;
        g_deg[i] = 0;
        if (i < EMB) g_meanfall[i] = 0.f;
    }
}

// ---------------- K1: node embeddings + projections ----------------
// block = 128 threads (4 warps), warp per node
__global__ void k_node(const float* __restrict__ node_f,
                       const float* __restrict__ W_veh,
                       const float* __restrict__ W_ped,
                       const float* __restrict__ W_att,
                       const float* __restrict__ W_upd) {
    __shared__ float sWv[EMB * EMB];   // transposed [c][o]
    __shared__ float sWp[EMB * EMB];   // transposed [c][o]
    __shared__ float sWun[EMB * EMB];  // Wu_n transposed [c][o]
    __shared__ float sWatt[HEADS * 128];

    int tid = threadIdx.x;
    for (int idx = tid; idx < EMB * EMB; idx += blockDim.x) {
        int o = idx >> 5, c = idx & 31;
        sWv [c * 32 + o] = W_veh[idx];             // W_veh[o][c]
        sWp [c * 32 + o] = W_ped[idx];
        sWun[c * 32 + o] = W_upd[o * 64 + 32 + c]; // Wu_n[o][c]
    }
    for (int idx = tid; idx < HEADS * 128; idx += blockDim.x) sWatt[idx] = W_att[idx];
    __syncthreads();

    int lane = tid & 31, w = tid >> 5;
    int i = blockIdx.x * 4 + w;
    if (i >= NN) return;

    float f = node_f[i * 32 + lane];
    bool is_ped = g_ped[i] != 0;
    bool is_veh = g_veh[i] != 0;
    const float* Wt = is_ped ? sWp : sWv;

    float acc = 0.f;
    #pragma unroll
    for (int c = 0; c < 32; c++)
        acc += __shfl_sync(0xffffffffu, f, c) * Wt[c * 32 + lane];
    float emb = (is_ped || is_veh) ? acc : 0.f;
    emb = leaky(emb);

    // tar[h] = emb . W_att[h, 0:32] ; nbr[h] = emb . W_att[h, 96:128]
    float t0 = emb * sWatt[0 * 128 + lane];
    float t1 = emb * sWatt[1 * 128 + lane];
    float t2 = emb * sWatt[2 * 128 + lane];
    float b0 = emb * sWatt[0 * 128 + 96 + lane];
    float b1 = emb * sWatt[1 * 128 + 96 + lane];
    float b2 = emb * sWatt[2 * 128 + 96 + lane];
    #pragma unroll
    for (int off = 16; off; off >>= 1) {
        t0 += __shfl_xor_sync(0xffffffffu, t0, off);
        t1 += __shfl_xor_sync(0xffffffffu, t1, off);
        t2 += __shfl_xor_sync(0xffffffffu, t2, off);
        b0 += __shfl_xor_sync(0xffffffffu, b0, off);
        b1 += __shfl_xor_sync(0xffffffffu, b1, off);
        b2 += __shfl_xor_sync(0xffffffffu, b2, off);
    }
    if (lane == 0) {
        g_tar[i * 3 + 0] = t0; g_tar[i * 3 + 1] = t1; g_tar[i * 3 + 2] = t2;
        g_nbr[i * 3 + 0] = b0; g_nbr[i * 3 + 1] = b1; g_nbr[i * 3 + 2] = b2;
    }

    // nbr_upd[o] = emb . Wu_n[o,:]
    float u = 0.f;
    #pragma unroll
    for (int c = 0; c < 32; c++)
        u += __shfl_sync(0xffffffffu, emb, c) * sWun[c * 32 + lane];
    g_nbrupd[i * 32 + lane] = u;
    atomicAdd(&g_meanfall[lane], leaky(u) * (1.0f / (float)NN));
}

// ---------------- K2: per-edge projections + degree counts ----------------
// block = 128 threads (4 warps), warp processes 8 edges -> 32 edges/block
__global__ void k_edge(const float* __restrict__ edge_attr,
                       const float* __restrict__ edge_type,
                       const float* __restrict__ W_ea,
                       const float* __restrict__ W_et,
                       const float* __restrict__ W_att,
                       const float* __restrict__ W_upd,
                       const int*   __restrict__ src) {
    __shared__ float sWea[64], sWet[64];
    __shared__ float sWe[HEADS * 64];     // W_edge[h][c], c<64
    __shared__ float sWueT[EMB * EMB];    // Wu_e transposed [c][o]

    int tid = threadIdx.x;
    for (int idx = tid; idx < 64; idx += blockDim.x) { sWea[idx] = W_ea[idx]; sWet[idx] = W_et[idx]; }
    for (int idx = tid; idx < HEADS * 64; idx += blockDim.x) {
        int h = idx / 64, c = idx % 64;
        sWe[idx] = W_att[h * 128 + 32 + c];
    }
    for (int idx = tid; idx < EMB * EMB; idx += blockDim.x) {
        int o = idx >> 5, c = idx & 31;
        sWueT[c * 32 + o] = W_upd[o * 64 + c];  // Wu_e[o][c]
    }
    __syncthreads();

    int lane = tid & 31, w = tid >> 5;
    #pragma unroll
    for (int r = 0; r < 8; r++) {
        int e = blockIdx.x * 32 + w * 8 + r;
        float ea0 = edge_attr[e * 2], ea1 = edge_attr[e * 2 + 1];
        float et0 = edge_type[e * 2], et1 = edge_type[e * 2 + 1];
        float embA = leaky(sWea[lane * 2] * ea0 + sWea[lane * 2 + 1] * ea1);
        float embT = leaky(sWet[lane * 2] * et0 + sWet[lane * 2 + 1] * et1);

        float s0 = embA * sWe[0 * 64 + lane] + embT * sWe[0 * 64 + 32 + lane];
        float s1 = embA * sWe[1 * 64 + lane] + embT * sWe[1 * 64 + 32 + lane];
        float s2 = embA * sWe[2 * 64 + lane] + embT * sWe[2 * 64 + 32 + lane];
        #pragma unroll
        for (int off = 16; off; off >>= 1) {
            s0 += __shfl_xor_sync(0xffffffffu, s0, off);
            s1 += __shfl_xor_sync(0xffffffffu, s1, off);
            s2 += __shfl_xor_sync(0xffffffffu, s2, off);
        }
        if (lane == 0) {
            g_escore[e * 4 + 0] = s0;
            g_escore[e * 4 + 1] = s1;
            g_escore[e * 4 + 2] = s2;
        }

        float u = 0.f;
        #pragma unroll
        for (int c = 0; c < 32; c++)
            u += __shfl_sync(0xffffffffu, embA, c) * sWueT[c * 32 + lane];
        g_eupd[e * 32 + lane] = u;

        if (lane == 0) atomicAdd(&g_deg[src[e]], 1);
    }
}

// ---------------- K3: exclusive scan of degrees -> row_ptr ----------------
// single block, 512 threads, 3 nodes/thread
__global__ void k_scan() {
    __shared__ int s[512];
    int tid = threadIdx.x;
    int a = g_deg[tid * 3], b = g_deg[tid * 3 + 1], c = g_deg[tid * 3 + 2];
    int tot = a + b + c;
    s[tid] = tot;
    __syncthreads();
    for (int off = 1; off < 512; off <<= 1) {
        int add = (tid >= off) ? s[tid - off] : 0;
        __syncthreads();
        s[tid] += add;
        __syncthreads();
    }
    int excl = tid ? s[tid - 1] : 0;
    int p0 = excl, p1 = excl + a, p2 = excl + a + b;
    g_rowptr[tid * 3 + 0] = p0; g_rowfill[tid * 3 + 0] = p0;
    g_rowptr[tid * 3 + 1] = p1; g_rowfill[tid * 3 + 1] = p1;
    g_rowptr[tid * 3 + 2] = p2; g_rowfill[tid * 3 + 2] = p2;
    if (tid == 511) g_rowptr[NN] = excl + tot;
}

// ---------------- K4: scatter edges into CSR order ----------------
__global__ void k_scatter(const int* __restrict__ src, const int* __restrict__ dst) {
    int e = blockIdx.x * blockDim.x + threadIdx.x;
    if (e >= NE) return;
    int s = src[e];
    int pos = atomicAdd(&g_rowfill[s], 1);
    g_dstS[pos] = dst[e];
    g_eidS[pos] = e;
}

// ---------------- K5: per-src-node attention + aggregation ----------------
// block per src node, 128 threads
__global__ void k_main(float* __restrict__ out) {
    __shared__ int   s_dst[MAXD];
    __shared__ float s_sc [MAXD * 3];
    __shared__ float s_upd[MAXD * EMB];
    __shared__ float s_part[4 * 3 * 32];
    __shared__ float s_m[12], s_s[12];

    int i = blockIdx.x;
    int tid = threadIdx.x, lane = tid & 31, w = tid >> 5;
    int start = g_rowptr[i];
    int d = g_rowptr[i + 1] - start;

    if (d == 0) {  // empty row: uniform attention over all nodes, edge part = 0
        if (tid < 96) out[i * 96 + tid] = g_meanfall[lane];
        return;
    }
    int dd = d < MAXD ? d : MAXD;

    // load row
    for (int k = w; k < dd; k += 4) {
        int e = g_eidS[start + k];
        if (lane == 0) s_dst[k] = g_dstS[start + k];
        if (lane < 3)  s_sc[k * 3 + lane] = g_escore[e * 4 + lane];
        s_upd[k * 32 + lane] = g_eupd[e * 32 + lane];
    }
    __syncthreads();

    // dedupe duplicate (src,dst) pairs: sum features into first occurrence
    for (int k = tid; k < dd; k += 128) {
        int dk = s_dst[k];
        int m = k;
        for (int j = 0; j < k; j++) if (s_dst[j] == dk) { m = j; break; }
        if (m != k) {
            float v0 = s_sc[k * 3 + 0], v1 = s_sc[k * 3 + 1], v2 = s_sc[k * 3 + 2];
            atomicAdd(&s_sc[m * 3 + 0], v0);
            atomicAdd(&s_sc[m * 3 + 1], v1);
            atomicAdd(&s_sc[m * 3 + 2], v2);
            #pragma unroll
            for (int o = 0; o < 32; o++)
                atomicAdd(&s_upd[m * 32 + o], s_upd[k * 32 + o]);
            s_sc[k * 3 + 0] = -1e30f; s_sc[k * 3 + 1] = -1e30f; s_sc[k * 3 + 2] = -1e30f;
        }
    }
    __syncthreads();

    // finalize scores: leaky(tar_i + edge + nbr_j)
    float ti0 = g_tar[i * 3 + 0], ti1 = g_tar[i * 3 + 1], ti2 = g_tar[i * 3 + 2];
    for (int k = tid; k < dd; k += 128) {
        if (s_sc[k * 3 + 0] > -1e29f) {
            int dk = s_dst[k];
            s_sc[k * 3 + 0] = leaky(ti0 + s_sc[k * 3 + 0] + g_nbr[dk * 3 + 0]);
            s_sc[k * 3 + 1] = leaky(ti1 + s_sc[k * 3 + 1] + g_nbr[dk * 3 + 1]);
            s_sc[k * 3 + 2] = leaky(ti2 + s_sc[k * 3 + 2] + g_nbr[dk * 3 + 2]);
        }
    }
    __syncthreads();

    // softmax per head over valid entries
    float lm0 = -1e30f, lm1 = -1e30f, lm2 = -1e30f;
    for (int k = tid; k < dd; k += 128) {
        lm0 = fmaxf(lm0, s_sc[k * 3 + 0]);
        lm1 = fmaxf(lm1, s_sc[k * 3 + 1]);
        lm2 = fmaxf(lm2, s_sc[k * 3 + 2]);
    }
    #pragma unroll
    for (int off = 16; off; off >>= 1) {
        lm0 = fmaxf(lm0, __shfl_xor_sync(0xffffffffu, lm0, off));
        lm1 = fmaxf(lm1, __shfl_xor_sync(0xffffffffu, lm1, off));
        lm2 = fmaxf(lm2, __shfl_xor_sync(0xffffffffu, lm2, off));
    }
    if (lane == 0) { s_m[w * 3 + 0] = lm0; s_m[w * 3 + 1] = lm1; s_m[w * 3 + 2] = lm2; }
    __syncthreads();
    float M0 = fmaxf(fmaxf(s_m[0], s_m[3]), fmaxf(s_m[6], s_m[9]));
    float M1 = fmaxf(fmaxf(s_m[1], s_m[4]), fmaxf(s_m[7], s_m[10]));
    float M2 = fmaxf(fmaxf(s_m[2], s_m[5]), fmaxf(s_m[8], s_m[11]));

    float ls0 = 0.f, ls1 = 0.f, ls2 = 0.f;
    for (int k = tid; k < dd; k += 128) {
        float e0 = __expf(s_sc[k * 3 + 0] - M0);
        float e1 = __expf(s_sc[k * 3 + 1] - M1);
        float e2 = __expf(s_sc[k * 3 + 2] - M2);
        s_sc[k * 3 + 0] = e0; s_sc[k * 3 + 1] = e1; s_sc[k * 3 + 2] = e2;
        ls0 += e0; ls1 += e1; ls2 += e2;
    }
    #pragma unroll
    for (int off = 16; off; off >>= 1) {
        ls0 += __shfl_xor_sync(0xffffffffu, ls0, off);
        ls1 += __shfl_xor_sync(0xffffffffu, ls1, off);
        ls2 += __shfl_xor_sync(0xffffffffu, ls2, off);
    }
    if (lane == 0) { s_s[w * 3 + 0] = ls0; s_s[w * 3 + 1] = ls1; s_s[w * 3 + 2] = ls2; }
    __syncthreads();
    float inv0 = 1.f / (s_s[0] + s_s[3] + s_s[6] + s_s[9]);
    float inv1 = 1.f / (s_s[1] + s_s[4] + s_s[7] + s_s[10]);
    float inv2 = 1.f / (s_s[2] + s_s[5] + s_s[8] + s_s[11]);

    // weighted aggregation: out[i,h,o] = sum_k attn[k,h] * leaky(upd_sum[k,o] + nbr_upd[dst,o])
    float a0acc = 0.f, a1acc = 0.f, a2acc = 0.f;
    for (int k = w; k < dd; k += 4) {
        float a0 = s_sc[k * 3 + 0] * inv0;
        float a1 = s_sc[k * 3 + 1] * inv1;
        float a2 = s_sc[k * 3 + 2] * inv2;
        int dk = s_dst[k];
        float u = leaky(s_upd[k * 32 + lane] + g_nbrupd[dk * 32 + lane]);
        a0acc += a0 * u; a1acc += a1 * u; a2acc += a2 * u;
    }
    s_part[(w * 3 + 0) * 32 + lane] = a0acc;
    s_part[(w * 3 + 1) * 32 + lane] = a1acc;
    s_part[(w * 3 + 2) * 32 + lane] = a2acc;
    __syncthreads();
    if (tid < 96) {
        int h = tid / 32, o = tid % 32;
        float r = s_part[(0 * 3 + h) * 32 + o] + s_part[(1 * 3 + h) * 32 + o]
                + s_part[(2 * 3 + h) * 32 + o] + s_part[(3 * 3 + h) * 32 + o];
        out[i * 96 + h * 32 + o] = r;
    }
}

// ---------------- launch ----------------
extern "C" void kernel_launch(void* const* d_in, const int* in_sizes, int n_in,
                              void* d_out, int out_size) {
    const float* node_f    = (const float*)d_in[0];
    const float* edge_attr = (const float*)d_in[1];
    const float* edge_type = (const float*)d_in[2];
    const float* W_veh     = (const float*)d_in[3];
    const float* W_ped     = (const float*)d_in[4];
    const float* W_ea      = (const float*)d_in[5];
    const float* W_et      = (const float*)d_in[6];
    const float* W_att     = (const float*)d_in[7];
    const float* W_upd     = (const float*)d_in[8];
    const int*   edge_index= (const int*)  d_in[9];
    const unsigned int* veh = (const unsigned int*)d_in[10];
    const unsigned int* ped = (const unsigned int*)d_in[11];

    const int* src = edge_index;        // edge_index[0, :]
    const int* dst = edge_index + NE;   // edge_index[1, :]
    float* out = (float*)d_out;

    k_mask<<<1, 512>>>(veh, ped);
    k_node<<<NN / 4, 128>>>(node_f, W_veh, W_ped, W_att, W_upd);
    k_edge<<<NE / 32, 128>>>(edge_attr, edge_type, W_ea, W_et, W_att, W_upd, src);
    k_scan<<<1, 512>>>();
    k_scatter<<<(NE + 255) / 256, 256>>>(src, dst);
    k_main<<<NN, 128>>>(out);
}

// round 3
// speedup vs baseline: 1.8312x; 1.8312x over previous
#include <cuda_runtime.h>

// ---------------- problem constants ----------------
#define NN      1536
#define NE      49152
#define EMB     32
#define SLOPE   0.2f
#define CAP     128            // bucket slots per node (max degree ~55)
#define NB_NODE (NN / 8)       // 192 node blocks, warp per node, 8 warps/block
#define NB_EDGE (NE / 128)     // 384 edge blocks, 16 edges per warp

// ---------------- device scratch (allocation-free, replay-safe) ----------
__device__ float  g_tar   [NN * 4];        // float4 per node: tar0..2
__device__ float  g_nbr   [NN * 4];        // float4 per node: nbr0..2
__device__ float  g_nbrupd[NN * EMB];
__device__ int    g_deg   [NN];            // zero at load; k_main resets each run
__device__ int    g_dstB  [NN * CAP];
__device__ float4 g_escB  [NN * CAP];
__device__ float  g_updB  [NN * CAP * EMB];

__device__ __forceinline__ float leaky(float x) { return x >= 0.f ? x : SLOPE * x; }

// ================= K1: fused node + edge preprocessing ===================
__global__ __launch_bounds__(256) void k_prep(
    const float* __restrict__ node_f,
    const float* __restrict__ edge_attr,
    const float* __restrict__ edge_type,
    const float* __restrict__ W_veh,
    const float* __restrict__ W_ped,
    const float* __restrict__ W_ea,
    const float* __restrict__ W_et,
    const float* __restrict__ W_att,
    const float* __restrict__ W_upd,
    const int*   __restrict__ src,
    const int*   __restrict__ dst,
    const unsigned int* __restrict__ veh_raw,
    const unsigned int* __restrict__ ped_raw)
{
    __shared__ float sW[3 * 1024 + 384];
    int tid = threadIdx.x, lane = tid & 31, w = tid >> 5;

    if (blockIdx.x < NB_NODE) {
        // ---------- node part: warp per node ----------
        __shared__ int s_notInt, s_notF32;
        if (tid == 0) { s_notInt = 0; s_notF32 = 0; }
        __syncthreads();
        // dtype-agnostic mask decode: inspect first 384 words (= min buffer size)
        for (int idx = tid; idx < 384; idx += 256) {
            unsigned int x = veh_raw[idx];
            if (!(x == 0u || x == 1u))          atomicOr(&s_notInt, 1);
            if (!(x == 0u || x == 0x3F800000u)) atomicOr(&s_notF32, 1);
        }
        float* sWv  = sW;          // [c][o]
        float* sWp  = sW + 1024;   // [c][o]
        float* sWun = sW + 2048;   // Wu_n [c][o]
        float* sWatt= sW + 3072;   // [h][128]
        for (int idx = tid; idx < 1024; idx += 256) {
            int o = idx >> 5, c = idx & 31;
            sWv [c * 32 + o] = W_veh[idx];
            sWp [c * 32 + o] = W_ped[idx];
            sWun[c * 32 + o] = W_upd[o * 64 + 32 + c];
        }
        for (int idx = tid; idx < 384; idx += 256) sWatt[idx] = W_att[idx];
        __syncthreads();
        int dtype = (!s_notInt) ? 0 : ((!s_notF32) ? 1 : 2);  // 0=i32,1=f32,2=u8

        int i = blockIdx.x * 8 + w;
        float f = node_f[i * 32 + lane];
        int v, p;
        if (dtype == 0)      { v = ((const int*)  veh_raw)[i] != 0;   p = ((const int*)  ped_raw)[i] != 0; }
        else if (dtype == 1) { v = ((const float*)veh_raw)[i] != 0.f; p = ((const float*)ped_raw)[i] != 0.f; }
        else                 { v = ((const unsigned char*)veh_raw)[i] != 0;
                               p = ((const unsigned char*)ped_raw)[i] != 0; }

        const float* Wt = p ? sWp : sWv;
        float acc = 0.f;
        #pragma unroll
        for (int c = 0; c < 32; c++)
            acc += __shfl_sync(0xffffffffu, f, c) * Wt[c * 32 + lane];
        float emb = (p || v) ? acc : 0.f;
        emb = leaky(emb);

        float t0 = emb * sWatt[lane],       t1 = emb * sWatt[128 + lane],      t2 = emb * sWatt[256 + lane];
        float b0 = emb * sWatt[96 + lane],  b1 = emb * sWatt[224 + lane],      b2 = emb * sWatt[352 + lane];
        #pragma unroll
        for (int off = 16; off; off >>= 1) {
            t0 += __shfl_xor_sync(0xffffffffu, t0, off);
            t1 += __shfl_xor_sync(0xffffffffu, t1, off);
            t2 += __shfl_xor_sync(0xffffffffu, t2, off);
            b0 += __shfl_xor_sync(0xffffffffu, b0, off);
            b1 += __shfl_xor_sync(0xffffffffu, b1, off);
            b2 += __shfl_xor_sync(0xffffffffu, b2, off);
        }
        if (lane == 0) {
            ((float4*)g_tar)[i] = make_float4(t0, t1, t2, 0.f);
            ((float4*)g_nbr)[i] = make_float4(b0, b1, b2, 0.f);
        }
        float u = 0.f;
        #pragma unroll
        for (int c = 0; c < 32; c++)
            u += __shfl_sync(0xffffffffu, emb, c) * sWun[c * 32 + lane];
        g_nbrupd[i * 32 + lane] = u;
    } else {
        // ---------- edge part: 16 edges per warp ----------
        float* sWea  = sW;         // [o][2]
        float* sWet  = sW + 64;
        float* sWe   = sW + 128;   // W_edge [h][64]
        float* sWueT = sW + 320;   // Wu_e [c][o]
        for (int idx = tid; idx < 64; idx += 256) { sWea[idx] = W_ea[idx]; sWet[idx] = W_et[idx]; }
        for (int idx = tid; idx < 192; idx += 256) {
            int h = idx / 64, c = idx % 64;
            sWe[idx] = W_att[h * 128 + 32 + c];
        }
        for (int idx = tid; idx < 1024; idx += 256) {
            int o = idx >> 5, c = idx & 31;
            sWueT[c * 32 + o] = W_upd[o * 64 + c];
        }
        __syncthreads();

        int ebase = (blockIdx.x - NB_NODE) * 128 + w * 16;
        #pragma unroll 4
        for (int r = 0; r < 16; r++) {
            int e = ebase + r;
            float ea0 = edge_attr[e * 2], ea1 = edge_attr[e * 2 + 1];
            float et0 = edge_type[e * 2], et1 = edge_type[e * 2 + 1];
            float embA = leaky(sWea[lane * 2] * ea0 + sWea[lane * 2 + 1] * ea1);
            float embT = leaky(sWet[lane * 2] * et0 + sWet[lane * 2 + 1] * et1);

            float s0 = embA * sWe[lane]       + embT * sWe[32 + lane];
            float s1 = embA * sWe[64 + lane]  + embT * sWe[96 + lane];
            float s2 = embA * sWe[128 + lane] + embT * sWe[160 + lane];
            #pragma unroll
            for (int off = 16; off; off >>= 1) {
                s0 += __shfl_xor_sync(0xffffffffu, s0, off);
                s1 += __shfl_xor_sync(0xffffffffu, s1, off);
                s2 += __shfl_xor_sync(0xffffffffu, s2, off);
            }
            float u = 0.f;
            #pragma unroll
            for (int c = 0; c < 32; c++)
                u += __shfl_sync(0xffffffffu, embA, c) * sWueT[c * 32 + lane];

            int s_node = 0, pos = 0;
            if (lane == 0) {
                s_node = src[e];
                pos = atomicAdd(&g_deg[s_node], 1);
            }
            s_node = __shfl_sync(0xffffffffu, s_node, 0);
            pos    = __shfl_sync(0xffffffffu, pos, 0);
            if (pos < CAP) {
                int slot = s_node * CAP + pos;
                g_updB[slot * 32 + lane] = u;
                if (lane == 0) {
                    g_dstB[slot] = dst[e];
                    g_escB[slot] = make_float4(s0, s1, s2, 0.f);
                }
            }
        }
    }
}

// ================= K2: per-src-node attention + aggregation ==============
__global__ __launch_bounds__(128) void k_main(float* __restrict__ out) {
    __shared__ int   s_dst[CAP];
    __shared__ float s_sc [CAP * 3];
    __shared__ float s_upd[CAP * EMB];
    __shared__ float s_part[12 * 32];
    __shared__ float s_m[12], s_s[12];

    int i = blockIdx.x;
    int tid = threadIdx.x, lane = tid & 31, w = tid >> 5;
    int d = g_deg[i];

    if (d == 0) {
        // empty row: uniform attention over all nodes; edge part = 0
        // out = mean_j leaky(nbrupd[j]) (same for all 3 heads)
        float acc = 0.f;
        for (int j = w; j < NN; j += 4) acc += leaky(g_nbrupd[j * 32 + lane]);
        s_part[w * 32 + lane] = acc;
        __syncthreads();
        if (tid < 96) {
            int o = tid & 31;
            out[i * 96 + tid] = (s_part[o] + s_part[32 + o] + s_part[64 + o] + s_part[96 + o]) * (1.f / NN);
        }
        return;
    }
    int dd = d < CAP ? d : CAP;

    // load row (contiguous bucket)
    for (int k = w; k < dd; k += 4) {
        int slot = i * CAP + k;
        s_upd[k * 32 + lane] = g_updB[slot * 32 + lane];
        if (lane == 0) {
            s_dst[k] = g_dstB[slot];
            float4 sc = g_escB[slot];
            s_sc[k * 3] = sc.x; s_sc[k * 3 + 1] = sc.y; s_sc[k * 3 + 2] = sc.z;
        }
    }
    __syncthreads();
    if (tid == 0) g_deg[i] = 0;   // reset for next graph replay (after barrier => all reads done)

    // dedupe duplicate (src,dst) pairs: sum features into first occurrence
    for (int k = tid; k < dd; k += 128) {
        int dk = s_dst[k];
        int m = k;
        for (int j = 0; j < k; j++) if (s_dst[j] == dk) { m = j; break; }
        if (m != k) {
            atomicAdd(&s_sc[m * 3 + 0], s_sc[k * 3 + 0]);
            atomicAdd(&s_sc[m * 3 + 1], s_sc[k * 3 + 1]);
            atomicAdd(&s_sc[m * 3 + 2], s_sc[k * 3 + 2]);
            #pragma unroll
            for (int o = 0; o < 32; o++)
                atomicAdd(&s_upd[m * 32 + o], s_upd[k * 32 + o]);
            s_sc[k * 3 + 0] = -1e30f; s_sc[k * 3 + 1] = -1e30f; s_sc[k * 3 + 2] = -1e30f;
        }
    }
    __syncthreads();

    // finalize scores: leaky(tar_i + edge + nbr_j)
    float4 ti = ((const float4*)g_tar)[i];
    for (int k = tid; k < dd; k += 128) {
        if (s_sc[k * 3 + 0] > -1e29f) {
            float4 nb = ((const float4*)g_nbr)[s_dst[k]];
            s_sc[k * 3 + 0] = leaky(ti.x + s_sc[k * 3 + 0] + nb.x);
            s_sc[k * 3 + 1] = leaky(ti.y + s_sc[k * 3 + 1] + nb.y);
            s_sc[k * 3 + 2] = leaky(ti.z + s_sc[k * 3 + 2] + nb.z);
        }
    }
    __syncthreads();

    // softmax per head
    float lm0 = -1e30f, lm1 = -1e30f, lm2 = -1e30f;
    for (int k = tid; k < dd; k += 128) {
        lm0 = fmaxf(lm0, s_sc[k * 3 + 0]);
        lm1 = fmaxf(lm1, s_sc[k * 3 + 1]);
        lm2 = fmaxf(lm2, s_sc[k * 3 + 2]);
    }
    #pragma unroll
    for (int off = 16; off; off >>= 1) {
        lm0 = fmaxf(lm0, __shfl_xor_sync(0xffffffffu, lm0, off));
        lm1 = fmaxf(lm1, __shfl_xor_sync(0xffffffffu, lm1, off));
        lm2 = fmaxf(lm2, __shfl_xor_sync(0xffffffffu, lm2, off));
    }
    if (lane == 0) { s_m[w * 3 + 0] = lm0; s_m[w * 3 + 1] = lm1; s_m[w * 3 + 2] = lm2; }
    __syncthreads();
    float M0 = fmaxf(fmaxf(s_m[0], s_m[3]), fmaxf(s_m[6], s_m[9]));
    float M1 = fmaxf(fmaxf(s_m[1], s_m[4]), fmaxf(s_m[7], s_m[10]));
    float M2 = fmaxf(fmaxf(s_m[2], s_m[5]), fmaxf(s_m[8], s_m[11]));

    float ls0 = 0.f, ls1 = 0.f, ls2 = 0.f;
    for (int k = tid; k < dd; k += 128) {
        float e0 = __expf(s_sc[k * 3 + 0] - M0);
        float e1 = __expf(s_sc[k * 3 + 1] - M1);
        float e2 = __expf(s_sc[k * 3 + 2] - M2);
        s_sc[k * 3 + 0] = e0; s_sc[k * 3 + 1] = e1; s_sc[k * 3 + 2] = e2;
        ls0 += e0; ls1 += e1; ls2 += e2;
    }
    #pragma unroll
    for (int off = 16; off; off >>= 1) {
        ls0 += __shfl_xor_sync(0xffffffffu, ls0, off);
        ls1 += __shfl_xor_sync(0xffffffffu, ls1, off);
        ls2 += __shfl_xor_sync(0xffffffffu, ls2, off);
    }
    if (lane == 0) { s_s[w * 3 + 0] = ls0; s_s[w * 3 + 1] = ls1; s_s[w * 3 + 2] = ls2; }
    __syncthreads();
    float inv0 = 1.f / (s_s[0] + s_s[3] + s_s[6] + s_s[9]);
    float inv1 = 1.f / (s_s[1] + s_s[4] + s_s[7] + s_s[10]);
    float inv2 = 1.f / (s_s[2] + s_s[5] + s_s[8] + s_s[11]);

    // weighted aggregation
    float a0 = 0.f, a1 = 0.f, a2 = 0.f;
    for (int k = w; k < dd; k += 4) {
        float p0 = s_sc[k * 3 + 0] * inv0;
        float p1 = s_sc[k * 3 + 1] * inv1;
        float p2 = s_sc[k * 3 + 2] * inv2;
        float u = leaky(s_upd[k * 32 + lane] + g_nbrupd[s_dst[k] * 32 + lane]);
        a0 += p0 * u; a1 += p1 * u; a2 += p2 * u;
    }
    s_part[(w * 3 + 0) * 32 + lane] = a0;
    s_part[(w * 3 + 1) * 32 + lane] = a1;
    s_part[(w * 3 + 2) * 32 + lane] = a2;
    __syncthreads();
    if (tid < 96) {
        int h = tid / 32, o = tid % 32;
        out[i * 96 + h * 32 + o] =
              s_part[(0 + h) * 32 + o] + s_part[(3 + h) * 32 + o]
            + s_part[(6 + h) * 32 + o] + s_part[(9 + h) * 32 + o];
    }
}

// ---------------- launch ----------------
extern "C" void kernel_launch(void* const* d_in, const int* in_sizes, int n_in,
                              void* d_out, int out_size) {
    const float* node_f    = (const float*)d_in[0];
    const float* edge_attr = (const float*)d_in[1];
    const float* edge_type = (const float*)d_in[2];
    const float* W_veh     = (const float*)d_in[3];
    const float* W_ped     = (const float*)d_in[4];
    const float* W_ea      = (const float*)d_in[5];
    const float* W_et      = (const float*)d_in[6];
    const float* W_att     = (const float*)d_in[7];
    const float* W_upd     = (const float*)d_in[8];
    const int*   edge_index= (const int*)  d_in[9];
    const unsigned int* veh = (const unsigned int*)d_in[10];
    const unsigned int* ped = (const unsigned int*)d_in[11];

    const int* src = edge_index;        // edge_index[0, :]
    const int* dst = edge_index + NE;   // edge_index[1, :]
    float* out = (float*)d_out;

    k_prep<<<NB_NODE + NB_EDGE, 256>>>(node_f, edge_attr, edge_type,
                                       W_veh, W_ped, W_ea, W_et, W_att, W_upd,
                                       src, dst, veh, ped);
    k_main<<<NN, 128>>>(out);
}